// round 2
// baseline (speedup 1.0000x reference)
#include <cuda_runtime.h>
#include <math.h>

#define BATCH 4
#define SEQ   1024
#define DIM   1024
#define NH    16
#define HD    64
#define MTOT  (BATCH*SEQ)   // 4096

// Scratch (allocation-free): head-layout projections + context, [B,H,S,HD]
__device__ float g_qh[BATCH*NH*SEQ*HD];
__device__ float g_kh[BATCH*NH*SEQ*HD];
__device__ float g_vh[BATCH*NH*SEQ*HD];
__device__ float g_ctx[BATCH*NH*SEQ*HD];

// ---------------------------------------------------------------------------
// QKV projection: Y = X @ W^T + b, scattered to [B,H,S,HD].
// 64x64 tile, BK=16, 256 threads, 4x4 microtile per thread.
// ---------------------------------------------------------------------------
__global__ __launch_bounds__(256) void proj_qkv(
    const float* __restrict__ xq, const float* __restrict__ xk, const float* __restrict__ xv,
    const float* __restrict__ Wq, const float* __restrict__ Wk, const float* __restrict__ Wv,
    const float* __restrict__ bq, const float* __restrict__ bk, const float* __restrict__ bv)
{
    int z = blockIdx.z;
    const float* X    = (z == 0) ? xq : (z == 1) ? xk : xv;
    const float* W    = (z == 0) ? Wq : (z == 1) ? Wk : Wv;
    const float* bias = (z == 0) ? bq : (z == 1) ? bk : bv;
    float* out        = (z == 0) ? g_qh : (z == 1) ? g_kh : g_vh;

    __shared__ float As[16][68];
    __shared__ float Bs[16][68];

    int t  = threadIdx.x;
    int tx = t & 15;       // 0..15 -> 4 cols each
    int ty = t >> 4;       // 0..15 -> 4 rows each
    int m0 = blockIdx.y * 64;
    int n0 = blockIdx.x * 64;

    int lr  = t >> 2;          // 0..63 tile row for loads
    int lc4 = (t & 3) * 4;     // 0,4,8,12 k-offset

    float acc[4][4];
    #pragma unroll
    for (int i = 0; i < 4; i++)
        #pragma unroll
        for (int j = 0; j < 4; j++) acc[i][j] = 0.0f;

    for (int k0 = 0; k0 < DIM; k0 += 16) {
        float4 av = *(const float4*)&X[(m0 + lr) * DIM + k0 + lc4];
        float4 bv = *(const float4*)&W[(n0 + lr) * DIM + k0 + lc4];
        As[lc4 + 0][lr] = av.x; As[lc4 + 1][lr] = av.y;
        As[lc4 + 2][lr] = av.z; As[lc4 + 3][lr] = av.w;
        Bs[lc4 + 0][lr] = bv.x; Bs[lc4 + 1][lr] = bv.y;
        Bs[lc4 + 2][lr] = bv.z; Bs[lc4 + 3][lr] = bv.w;
        __syncthreads();

        #pragma unroll
        for (int kk = 0; kk < 16; kk++) {
            float4 a4 = *(const float4*)&As[kk][ty * 4];
            float4 b4 = *(const float4*)&Bs[kk][tx * 4];
            float a[4] = {a4.x, a4.y, a4.z, a4.w};
            float b[4] = {b4.x, b4.y, b4.z, b4.w};
            #pragma unroll
            for (int i = 0; i < 4; i++)
                #pragma unroll
                for (int j = 0; j < 4; j++)
                    acc[i][j] += a[i] * b[j];
        }
        __syncthreads();
    }

    #pragma unroll
    for (int i = 0; i < 4; i++) {
        int m = m0 + ty * 4 + i;
        int b_ = m >> 10, s = m & (SEQ - 1);
        #pragma unroll
        for (int j = 0; j < 4; j++) {
            int n = n0 + tx * 4 + j;
            int h = n >> 6, d = n & 63;
            out[(((b_ * NH + h) * SEQ + s) << 6) + d] = acc[i][j] + bias[n];
        }
    }
}

// ---------------------------------------------------------------------------
// Attention: per block = one (b,h) pair x 16 query rows.
// scores (16x1024) in smem, triple softmax, then A @ V.
// ---------------------------------------------------------------------------
#define AROWS 16
#define KVSTRIDE 65
#define ATTN_SMEM_FLOATS (AROWS*SEQ + AROWS*HD + 64*KVSTRIDE)

__global__ __launch_bounds__(256) void attn_kernel(const float* __restrict__ mask)
{
    extern __shared__ float sm[];
    float* sc = sm;                        // AROWS * 1024
    float* qr = sm + AROWS * SEQ;          // AROWS * 64
    float* kv = qr + AROWS * HD;           // 64 * 65

    int t  = threadIdx.x;
    int bh = blockIdx.y;
    int b_ = bh >> 4;
    int q0 = blockIdx.x * AROWS;

    const float* Q = g_qh + (size_t)bh * SEQ * HD;
    const float* K = g_kh + (size_t)bh * SEQ * HD;
    const float* V = g_vh + (size_t)bh * SEQ * HD;

    // load 16 q rows
    {
        int r = t >> 4, c4 = (t & 15) * 4;
        *(float4*)&qr[r * HD + c4] = *(const float4*)&Q[(q0 + r) * HD + c4];
    }

    int c  = t & 63;        // key/col (or headdim in AV phase)
    int rg = t >> 6;        // row group 0..3 (rows rg*4 .. rg*4+3)

    // ---- scores = Q K^T / 8 + mask ----
    for (int j0 = 0; j0 < SEQ; j0 += 64) {
        __syncthreads();
        #pragma unroll
        for (int l = 0; l < 4; l++) {
            int idx = t + l * 256;
            int j = idx >> 4, d4 = (idx & 15) * 4;
            float4 v = *(const float4*)&K[(j0 + j) * HD + d4];
            kv[j * KVSTRIDE + d4 + 0] = v.x;
            kv[j * KVSTRIDE + d4 + 1] = v.y;
            kv[j * KVSTRIDE + d4 + 2] = v.z;
            kv[j * KVSTRIDE + d4 + 3] = v.w;
        }
        __syncthreads();

        float acc[4] = {0.f, 0.f, 0.f, 0.f};
        #pragma unroll
        for (int d = 0; d < HD; d++) {
            float kval = kv[c * KVSTRIDE + d];
            #pragma unroll
            for (int i = 0; i < 4; i++)
                acc[i] += qr[(rg * 4 + i) * HD + d] * kval;
        }
        float mk = mask[b_ * SEQ + j0 + c];
        #pragma unroll
        for (int i = 0; i < 4; i++)
            sc[(rg * 4 + i) * SEQ + j0 + c] = acc[i] * 0.125f + mk;
    }
    __syncthreads();

    // ---- triple softmax (warp per 2 rows) ----
    int warp = t >> 5, lane = t & 31;
    #pragma unroll
    for (int it = 0; it < 3; it++) {
        for (int rr = 0; rr < 2; rr++) {
            int r = warp * 2 + rr;
            float* row = sc + r * SEQ;
            float mx = -INFINITY;
            for (int j = lane; j < SEQ; j += 32) mx = fmaxf(mx, row[j]);
            #pragma unroll
            for (int o = 16; o; o >>= 1) mx = fmaxf(mx, __shfl_xor_sync(0xffffffffu, mx, o));
            float sum = 0.f;
            for (int j = lane; j < SEQ; j += 32) {
                float e = __expf(row[j] - mx);
                row[j] = e;
                sum += e;
            }
            #pragma unroll
            for (int o = 16; o; o >>= 1) sum += __shfl_xor_sync(0xffffffffu, sum, o);
            float inv = 1.0f / sum;
            for (int j = lane; j < SEQ; j += 32) row[j] *= inv;
        }
        __syncwarp();
    }
    __syncthreads();

    // ---- context = attn @ V ----
    float oacc[4] = {0.f, 0.f, 0.f, 0.f};
    for (int j0 = 0; j0 < SEQ; j0 += 64) {
        __syncthreads();
        #pragma unroll
        for (int l = 0; l < 4; l++) {
            int idx = t + l * 256;
            int j = idx >> 4, d4 = (idx & 15) * 4;
            float4 v = *(const float4*)&V[(j0 + j) * HD + d4];
            kv[j * KVSTRIDE + d4 + 0] = v.x;
            kv[j * KVSTRIDE + d4 + 1] = v.y;
            kv[j * KVSTRIDE + d4 + 2] = v.z;
            kv[j * KVSTRIDE + d4 + 3] = v.w;
        }
        __syncthreads();

        #pragma unroll
        for (int j = 0; j < 64; j++) {
            float vval = kv[j * KVSTRIDE + c];
            #pragma unroll
            for (int i = 0; i < 4; i++)
                oacc[i] += sc[(rg * 4 + i) * SEQ + j0 + j] * vval;
        }
    }
    #pragma unroll
    for (int i = 0; i < 4; i++)
        g_ctx[((size_t)bh * SEQ + q0 + rg * 4 + i) * HD + c] = oacc[i];
}

// ---------------------------------------------------------------------------
// Output projection: Y = ctx(gathered to [B,S,DIM]) @ Wo^T + bo -> d_out
// ---------------------------------------------------------------------------
__global__ __launch_bounds__(256) void out_proj(
    const float* __restrict__ Wo, const float* __restrict__ bo, float* __restrict__ out)
{
    __shared__ float As[16][68];
    __shared__ float Bs[16][68];

    int t  = threadIdx.x;
    int tx = t & 15;
    int ty = t >> 4;
    int m0 = blockIdx.y * 64;
    int n0 = blockIdx.x * 64;

    int lr  = t >> 2;
    int lc4 = (t & 3) * 4;

    float acc[4][4];
    #pragma unroll
    for (int i = 0; i < 4; i++)
        #pragma unroll
        for (int j = 0; j < 4; j++) acc[i][j] = 0.0f;

    int m = m0 + lr;
    int b_ = m >> 10, s = m & (SEQ - 1);

    for (int k0 = 0; k0 < DIM; k0 += 16) {
        int k = k0 + lc4;
        int h = k >> 6, d = k & 63;
        float4 av = *(const float4*)&g_ctx[(((b_ * NH + h) * SEQ + s) << 6) + d];
        float4 bv = *(const float4*)&Wo[(n0 + lr) * DIM + k0 + lc4];
        As[lc4 + 0][lr] = av.x; As[lc4 + 1][lr] = av.y;
        As[lc4 + 2][lr] = av.z; As[lc4 + 3][lr] = av.w;
        Bs[lc4 + 0][lr] = bv.x; Bs[lc4 + 1][lr] = bv.y;
        Bs[lc4 + 2][lr] = bv.z; Bs[lc4 + 3][lr] = bv.w;
        __syncthreads();

        #pragma unroll
        for (int kk = 0; kk < 16; kk++) {
            float4 a4 = *(const float4*)&As[kk][ty * 4];
            float4 b4 = *(const float4*)&Bs[kk][tx * 4];
            float a[4] = {a4.x, a4.y, a4.z, a4.w};
            float b[4] = {b4.x, b4.y, b4.z, b4.w};
            #pragma unroll
            for (int i = 0; i < 4; i++)
                #pragma unroll
                for (int j = 0; j < 4; j++)
                    acc[i][j] += a[i] * b[j];
        }
        __syncthreads();
    }

    #pragma unroll
    for (int i = 0; i < 4; i++) {
        int mm = m0 + ty * 4 + i;
        #pragma unroll
        for (int j = 0; j < 4; j++) {
            int n = n0 + tx * 4 + j;
            out[mm * DIM + n] = acc[i][j] + bo[n];
        }
    }
}

// ---------------------------------------------------------------------------
extern "C" void kernel_launch(void* const* d_in, const int* in_sizes, int n_in,
                              void* d_out, int out_size)
{
    const float* q    = (const float*)d_in[0];
    const float* k    = (const float*)d_in[1];
    const float* v    = (const float*)d_in[2];
    const float* mask = (const float*)d_in[3];
    const float* Wq   = (const float*)d_in[4];
    const float* bq   = (const float*)d_in[5];
    const float* Wk   = (const float*)d_in[6];
    const float* bk   = (const float*)d_in[7];
    const float* Wv   = (const float*)d_in[8];
    const float* bv   = (const float*)d_in[9];
    const float* Wo   = (const float*)d_in[10];
    const float* bo   = (const float*)d_in[11];
    float* out = (float*)d_out;

    // QKV projections (z = 0,1,2)
    proj_qkv<<<dim3(DIM / 64, MTOT / 64, 3), 256>>>(q, k, v, Wq, Wk, Wv, bq, bk, bv);

    // Attention (86272 B dynamic smem; attribute call is eager + idempotent)
    static int smem_attr_set = -1;
    int smem = ATTN_SMEM_FLOATS * (int)sizeof(float);
    if (smem_attr_set != smem) {
        cudaFuncSetAttribute(attn_kernel, cudaFuncAttributeMaxDynamicSharedMemorySize, smem);
        smem_attr_set = smem;
    }
    attn_kernel<<<dim3(SEQ / AROWS, BATCH * NH), 256, smem>>>(mask);

    // Output projection
    out_proj<<<dim3(DIM / 64, MTOT / 64), 256>>>(Wo, bo, out);
}